// round 7
// baseline (speedup 1.0000x reference)
#include <cuda_runtime.h>
#include <math.h>

// Problem dims
#define Bb 32
#define LC 2048
#define LQ 256
#define Dd 256

// GEMM tiling
#define BM 128
#define BN 128
#define KC 32
#define PAD 4

// ---------------- scratch (device globals; no allocations allowed) ----------------
__device__ float g_E[(size_t)Bb * LC * LQ];          // exp(sim), 0 at masked  (67 MB)
__device__ float g_T[(size_t)Bb * LQ * Dd];          // T = SS^T @ context      (8 MB)
__device__ float g_sc[Bb * LC];
__device__ float g_sq[Bb * LQ];
__device__ float g_rowsum_part[Bb * 2 * LC];         // per q-tile partials
__device__ float g_rowsum[Bb * LC];
__device__ float g_colsum_part[Bb * 16 * LQ];        // per c-tile partials
__device__ float g_colsum[Bb * LQ];
__device__ float g_qmean[Bb * Dd];
__device__ float g_cmean_part[Bb * 8 * Dd];
__device__ float g_cmean[Bb * Dd];
__device__ float g_tmean[Bb * Dd];
__device__ unsigned char g_cm[Bb * LC];
__device__ unsigned char g_qm[Bb * LQ];
__device__ int g_is32;

// ---------------- mask dtype detection + canonicalization ----------------
// numpy bool -> 1 byte/elem (random 0/1 bytes). If harness widened to int32,
// every element is {v,0,0,0} little-endian -> bytes at (i%4!=0) are all zero.
__global__ void k_detect(const unsigned char* __restrict__ cm) {
    if (threadIdx.x == 0 && blockIdx.x == 0) {
        int is32 = 1;
        for (int i = 0; i < 4096; i++) {
            if ((i & 3) && cm[i]) { is32 = 0; break; }
        }
        g_is32 = is32;
    }
}

__global__ void k_cvt_mask(const void* __restrict__ cm, const void* __restrict__ qm) {
    int i = blockIdx.x * 256 + threadIdx.x;
    int is32 = g_is32;
    if (i < Bb * LC) {
        g_cm[i] = is32 ? (unsigned char)(((const int*)cm)[i] != 0)
                       : (unsigned char)(((const unsigned char*)cm)[i] != 0);
    }
    if (i < Bb * LQ) {
        g_qm[i] = is32 ? (unsigned char)(((const int*)qm)[i] != 0)
                       : (unsigned char)(((const unsigned char*)qm)[i] != 0);
    }
}

// ---------------- K0a: sc = context @ wc, sq = query @ wq ----------------
__global__ void k0_rowdots(const float* __restrict__ ctx, const float* __restrict__ qry,
                           const float* __restrict__ w0) {
    int warp = (blockIdx.x * blockDim.x + threadIdx.x) >> 5;
    int lane = threadIdx.x & 31;
    const int nC = Bb * LC;
    const float* src;
    const float* wgt;
    float* dst;
    if (warp < nC) {
        src = ctx + (size_t)warp * Dd; wgt = w0; dst = g_sc + warp;
    } else {
        int r = warp - nC;
        if (r >= Bb * LQ) return;
        src = qry + (size_t)r * Dd; wgt = w0 + Dd; dst = g_sq + r;
    }
    float s = 0.f;
#pragma unroll
    for (int i = 0; i < 2; i++) {
        int idx = (lane + 32 * i) * 4;
        float4 v = *(const float4*)(src + idx);
        float4 w = *(const float4*)(wgt + idx);
        s += v.x * w.x + v.y * w.y + v.z * w.z + v.w * w.w;
    }
#pragma unroll
    for (int o = 16; o; o >>= 1) s += __shfl_xor_sync(0xffffffffu, s, o);
    if (lane == 0) *dst = s;
}

// ---------------- K0b: qmean, cmean partials ----------------
__global__ void k0_means(const float* __restrict__ ctx, const float* __restrict__ qry) {
    int b = blockIdx.x, y = blockIdx.y, d = threadIdx.x;  // 256 threads = D
    if (y == 0) {
        const float* p = qry + (size_t)b * LQ * Dd + d;
        float s0 = 0, s1 = 0, s2 = 0, s3 = 0, s4 = 0, s5 = 0, s6 = 0, s7 = 0;
        for (int q = 0; q < LQ; q += 8) {
            s0 += p[(size_t)(q + 0) * Dd]; s1 += p[(size_t)(q + 1) * Dd];
            s2 += p[(size_t)(q + 2) * Dd]; s3 += p[(size_t)(q + 3) * Dd];
            s4 += p[(size_t)(q + 4) * Dd]; s5 += p[(size_t)(q + 5) * Dd];
            s6 += p[(size_t)(q + 6) * Dd]; s7 += p[(size_t)(q + 7) * Dd];
        }
        g_qmean[b * Dd + d] = (((s0 + s1) + (s2 + s3)) + ((s4 + s5) + (s6 + s7))) * (1.0f / LQ);
    } else {
        int chunk = y - 1;  // 8 chunks of 256 context rows
        const float* p = ctx + ((size_t)b * LC + chunk * 256) * Dd + d;
        float s0 = 0, s1 = 0, s2 = 0, s3 = 0, s4 = 0, s5 = 0, s6 = 0, s7 = 0;
        for (int c = 0; c < 256; c += 8) {
            s0 += p[(size_t)(c + 0) * Dd]; s1 += p[(size_t)(c + 1) * Dd];
            s2 += p[(size_t)(c + 2) * Dd]; s3 += p[(size_t)(c + 3) * Dd];
            s4 += p[(size_t)(c + 4) * Dd]; s5 += p[(size_t)(c + 5) * Dd];
            s6 += p[(size_t)(c + 6) * Dd]; s7 += p[(size_t)(c + 7) * Dd];
        }
        g_cmean_part[((size_t)b * 8 + chunk) * Dd + d] =
            ((s0 + s1) + (s2 + s3)) + ((s4 + s5) + (s6 + s7));
    }
}

// ---------------- K1: E = exp(sim) (masked -> 0) + row/col partial sums ----------------
__global__ __launch_bounds__(256)
void k1_exp(const float* __restrict__ ctx, const float* __restrict__ qry,
            const float* __restrict__ w0) {
    int b = blockIdx.z;
    int cblk = blockIdx.x * BM;   // 16 tiles
    int qblk = blockIdx.y * BN;   // 2 tiles
    __shared__ float As[KC][BM + PAD];
    __shared__ float Bs[KC][BN + PAD];
    __shared__ float colred[16][BN];
    int tid = threadIdx.x;
    int tx = tid & 15, ty = tid >> 4;
    float acc[8][8];
#pragma unroll
    for (int i = 0; i < 8; i++)
#pragma unroll
        for (int j = 0; j < 8; j++) acc[i][j] = 0.f;

    const float* wm = w0 + 2 * Dd;
    const float* Ap = ctx + ((size_t)b * LC + cblk) * Dd;
    const float* Bp = qry + ((size_t)b * LQ + qblk) * Dd;

    for (int k0 = 0; k0 < Dd; k0 += KC) {
#pragma unroll
        for (int r = 0; r < 4; r++) {
            int u = tid + 256 * r;          // 1024 float4 slots per matrix
            int row = u >> 3;
            int kq = (u & 7) * 4;
            float4 v = *(const float4*)(Ap + (size_t)row * Dd + k0 + kq);
            float4 w = *(const float4*)(wm + k0 + kq);
            As[kq + 0][row] = v.x * w.x; As[kq + 1][row] = v.y * w.y;
            As[kq + 2][row] = v.z * w.z; As[kq + 3][row] = v.w * w.w;
            float4 q4 = *(const float4*)(Bp + (size_t)row * Dd + k0 + kq);
            Bs[kq + 0][row] = q4.x; Bs[kq + 1][row] = q4.y;
            Bs[kq + 2][row] = q4.z; Bs[kq + 3][row] = q4.w;
        }
        __syncthreads();
#pragma unroll 4
        for (int kk = 0; kk < KC; kk++) {
            float a[8], bv[8];
            *(float4*)&a[0] = *(const float4*)&As[kk][ty * 8];
            *(float4*)&a[4] = *(const float4*)&As[kk][ty * 8 + 4];
            *(float4*)&bv[0] = *(const float4*)&Bs[kk][tx * 8];
            *(float4*)&bv[4] = *(const float4*)&Bs[kk][tx * 8 + 4];
#pragma unroll
            for (int i = 0; i < 8; i++)
#pragma unroll
                for (int j = 0; j < 8; j++) acc[i][j] += a[i] * bv[j];
        }
        __syncthreads();
    }

    // epilogue: sim = acc + sc + sq; mask; E = exp(sim)
    float sqv[8];
    int qmv[8];
#pragma unroll
    for (int j = 0; j < 8; j++) {
        int q = qblk + tx * 8 + j;
        sqv[j] = g_sq[b * LQ + q];
        qmv[j] = g_qm[b * LQ + q];
    }
    float colpart[8];
#pragma unroll
    for (int j = 0; j < 8; j++) colpart[j] = 0.f;

#pragma unroll
    for (int i = 0; i < 8; i++) {
        int c = cblk + ty * 8 + i;
        float scv = g_sc[b * LC + c];
        int cmv = g_cm[b * LC + c];
        float e[8];
        float rowp = 0.f;
#pragma unroll
        for (int j = 0; j < 8; j++) {
            float s = acc[i][j] + scv + sqv[j];
            float ev = (cmv | qmv[j]) ? 0.f : __expf(s);
            e[j] = ev;
            rowp += ev;
            colpart[j] += ev;
        }
        float* ep = g_E + ((size_t)(b * LC + c)) * LQ + qblk + tx * 8;
        *(float4*)ep       = make_float4(e[0], e[1], e[2], e[3]);
        *(float4*)(ep + 4) = make_float4(e[4], e[5], e[6], e[7]);
        // reduce over the 16 tx-lanes (same ty => same 16-lane segment)
#pragma unroll
        for (int o = 8; o; o >>= 1) rowp += __shfl_xor_sync(0xffffffffu, rowp, o, 16);
        if (tx == 0) g_rowsum_part[((size_t)b * 2 + blockIdx.y) * LC + c] = rowp;
    }
#pragma unroll
    for (int j = 0; j < 8; j++) colred[ty][tx * 8 + j] = colpart[j];
    __syncthreads();
    if (tid < BN) {
        float s = 0.f;
#pragma unroll
        for (int t = 0; t < 16; t++) s += colred[t][tid];
        g_colsum_part[((size_t)b * 16 + blockIdx.x) * LQ + qblk + tid] = s;
    }
}

// ---------------- K2: deterministic partial reductions ----------------
__global__ void k2_reduce() {
    int b = blockIdx.x, tid = threadIdx.x;  // 256 threads
    for (int c = tid; c < LC; c += 256) {
        g_rowsum[b * LC + c] = g_rowsum_part[((size_t)b * 2 + 0) * LC + c] +
                               g_rowsum_part[((size_t)b * 2 + 1) * LC + c];
    }
    {
        int q = tid;
        float s = 0.f;
#pragma unroll
        for (int t = 0; t < 16; t++) s += g_colsum_part[((size_t)b * 16 + t) * LQ + q];
        g_colsum[b * LQ + q] = s;
    }
    {
        int d = tid;
        float s = 0.f;
#pragma unroll
        for (int t = 0; t < 8; t++) s += g_cmean_part[((size_t)b * 8 + t) * Dd + d];
        g_cmean[b * Dd + d] = s * (1.0f / LC);
    }
}

// ---------------- K3: T[q][d] = (1/colsum) * sum_c E[c][q]*ctx[c][d] (fallback cmean) -----
__global__ __launch_bounds__(256)
void k3_T(const float* __restrict__ ctx) {
    int b = blockIdx.z;
    int qblk = blockIdx.x * BM;  // 2 tiles
    int dblk = blockIdx.y * BN;  // 2 tiles
    __shared__ float As[KC][BM + PAD];
    __shared__ float Bs[KC][BN + PAD];
    int tid = threadIdx.x, tx = tid & 15, ty = tid >> 4;
    float acc[8][8];
#pragma unroll
    for (int i = 0; i < 8; i++)
#pragma unroll
        for (int j = 0; j < 8; j++) acc[i][j] = 0.f;

    const float* Ep = g_E + (size_t)b * LC * LQ;
    const float* Cp = ctx + (size_t)b * LC * Dd;

    for (int k0 = 0; k0 < LC; k0 += KC) {
#pragma unroll
        for (int r = 0; r < 4; r++) {
            int u = tid + 256 * r;
            int kk = u >> 5;
            int m4 = (u & 31) * 4;
            *(float4*)&As[kk][m4] = *(const float4*)(Ep + (size_t)(k0 + kk) * LQ + qblk + m4);
            *(float4*)&Bs[kk][m4] = *(const float4*)(Cp + (size_t)(k0 + kk) * Dd + dblk + m4);
        }
        __syncthreads();
#pragma unroll 4
        for (int kk = 0; kk < KC; kk++) {
            float a[8], bv[8];
            *(float4*)&a[0] = *(const float4*)&As[kk][ty * 8];
            *(float4*)&a[4] = *(const float4*)&As[kk][ty * 8 + 4];
            *(float4*)&bv[0] = *(const float4*)&Bs[kk][tx * 8];
            *(float4*)&bv[4] = *(const float4*)&Bs[kk][tx * 8 + 4];
#pragma unroll
            for (int i = 0; i < 8; i++)
#pragma unroll
                for (int j = 0; j < 8; j++) acc[i][j] += a[i] * bv[j];
        }
        __syncthreads();
    }

#pragma unroll
    for (int i = 0; i < 8; i++) {
        int q = qblk + ty * 8 + i;
        float cs = g_colsum[b * LQ + q];
        float* Tp = g_T + ((size_t)b * LQ + q) * Dd + dblk + tx * 8;
        if (cs > 0.f) {
            float inv = 1.0f / cs;
            *(float4*)Tp = make_float4(acc[i][0] * inv, acc[i][1] * inv,
                                       acc[i][2] * inv, acc[i][3] * inv);
            *(float4*)(Tp + 4) = make_float4(acc[i][4] * inv, acc[i][5] * inv,
                                             acc[i][6] * inv, acc[i][7] * inv);
        } else {
            const float* fb = g_cmean + b * Dd + dblk + tx * 8;
            *(float4*)Tp = make_float4(fb[0], fb[1], fb[2], fb[3]);
            *(float4*)(Tp + 4) = make_float4(fb[4], fb[5], fb[6], fb[7]);
        }
    }
}

// ---------------- K3b: tmean = mean_q T ----------------
__global__ void k3b_tmean() {
    int b = blockIdx.x, d = threadIdx.x;  // 256 threads
    const float* p = g_T + (size_t)b * LQ * Dd + d;
    float s0 = 0, s1 = 0, s2 = 0, s3 = 0;
    for (int q = 0; q < LQ; q += 4) {
        s0 += p[(size_t)(q + 0) * Dd]; s1 += p[(size_t)(q + 1) * Dd];
        s2 += p[(size_t)(q + 2) * Dd]; s3 += p[(size_t)(q + 3) * Dd];
    }
    g_tmean[b * Dd + d] = ((s0 + s1) + (s2 + s3)) * (1.0f / LQ);
}

// ---------------- K4: A = E@query / rowsum ; Bmat = E@T / rowsum (uniform fallbacks) -----
__global__ __launch_bounds__(256)
void k4_out(const float* __restrict__ qry, float* __restrict__ out) {
    int b = blockIdx.z;
    int cblk = blockIdx.x * BM;              // 16 tiles
    int sel = blockIdx.y >> 1;               // 0 = A, 1 = Bmat
    int dblk = (blockIdx.y & 1) * BN;        // 2 tiles
    const float* Bsrc = sel ? (g_T + (size_t)b * LQ * Dd) : (qry + (size_t)b * LQ * Dd);
    const float* fb = (sel ? g_tmean : g_qmean) + b * Dd;
    float* op = out + (size_t)sel * Bb * LC * Dd + (size_t)b * LC * Dd;

    __shared__ float As[KC][BM + PAD];
    __shared__ float Bs[KC][BN + PAD];
    int tid = threadIdx.x, tx = tid & 15, ty = tid >> 4;
    float acc[8][8];
#pragma unroll
    for (int i = 0; i < 8; i++)
#pragma unroll
        for (int j = 0; j < 8; j++) acc[i][j] = 0.f;

    const float* Ep = g_E + ((size_t)b * LC + cblk) * LQ;

    for (int k0 = 0; k0 < LQ; k0 += KC) {
#pragma unroll
        for (int r = 0; r < 4; r++) {
            int u = tid + 256 * r;
            // A tile: E rows (k = q contiguous) -> transpose into As[k][m]
            int row = u >> 3;
            int kq = (u & 7) * 4;
            float4 v = *(const float4*)(Ep + (size_t)row * LQ + k0 + kq);
            As[kq + 0][row] = v.x; As[kq + 1][row] = v.y;
            As[kq + 2][row] = v.z; As[kq + 3][row] = v.w;
            // B tile: Bsrc[k=q][n=d] directly
            int kk = u >> 5;
            int m4 = (u & 31) * 4;
            *(float4*)&Bs[kk][m4] = *(const float4*)(Bsrc + (size_t)(k0 + kk) * Dd + dblk + m4);
        }
        __syncthreads();
#pragma unroll 4
        for (int kk = 0; kk < KC; kk++) {
            float a[8], bv[8];
            *(float4*)&a[0] = *(const float4*)&As[kk][ty * 8];
            *(float4*)&a[4] = *(const float4*)&As[kk][ty * 8 + 4];
            *(float4*)&bv[0] = *(const float4*)&Bs[kk][tx * 8];
            *(float4*)&bv[4] = *(const float4*)&Bs[kk][tx * 8 + 4];
#pragma unroll
            for (int i = 0; i < 8; i++)
#pragma unroll
                for (int j = 0; j < 8; j++) acc[i][j] += a[i] * bv[j];
        }
        __syncthreads();
    }

#pragma unroll
    for (int i = 0; i < 8; i++) {
        int c = cblk + ty * 8 + i;
        float rs = g_rowsum[b * LC + c];
        float* dst = op + (size_t)c * Dd + dblk + tx * 8;
        if (rs > 0.f) {
            float inv = 1.0f / rs;
            *(float4*)dst = make_float4(acc[i][0] * inv, acc[i][1] * inv,
                                        acc[i][2] * inv, acc[i][3] * inv);
            *(float4*)(dst + 4) = make_float4(acc[i][4] * inv, acc[i][5] * inv,
                                              acc[i][6] * inv, acc[i][7] * inv);
        } else {
            const float* f = fb + dblk + tx * 8;
            *(float4*)dst = make_float4(f[0], f[1], f[2], f[3]);
            *(float4*)(dst + 4) = make_float4(f[4], f[5], f[6], f[7]);
        }
    }
}

// ---------------- launcher ----------------
extern "C" void kernel_launch(void* const* d_in, const int* in_sizes, int n_in,
                              void* d_out, int out_size) {
    const float* ctx = (const float*)d_in[0];
    const float* qry = (const float*)d_in[1];
    const void* cmask = d_in[2];
    const void* qmask = d_in[3];
    const float* w0 = (const float*)d_in[4];
    float* out = (float*)d_out;

    k_detect<<<1, 32>>>((const unsigned char*)cmask);
    k_cvt_mask<<<(Bb * LC + 255) / 256, 256>>>(cmask, qmask);
    k0_rowdots<<<(Bb * (LC + LQ)) / 8, 256>>>(ctx, qry, w0);
    k0_means<<<dim3(Bb, 9), 256>>>(ctx, qry);
    k1_exp<<<dim3(LC / BM, LQ / BN, Bb), 256>>>(ctx, qry, w0);
    k2_reduce<<<Bb, 256>>>();
    k3_T<<<dim3(LQ / BM, Dd / BN, Bb), 256>>>(ctx);
    k3b_tmean<<<Bb, 256>>>();
    k4_out<<<dim3(LC / BM, 4, Bb), 256>>>(qry, out);
}

// round 8
// speedup vs baseline: 1.0019x; 1.0019x over previous
#include <cuda_runtime.h>
#include <math.h>

// Problem dims
#define Bb 32
#define LC 2048
#define LQ 256
#define Dd 256

// GEMM tiling
#define BM 128
#define BN 128
#define KC 32
#define PAD 4

// ---------------- scratch (device globals; no allocations allowed) ----------------
__device__ float g_E[(size_t)Bb * LC * LQ];          // exp(sim), 0 at masked  (67 MB)
__device__ float g_T[(size_t)Bb * LQ * Dd];          // T = SS^T @ context      (8 MB)
__device__ float g_sc[Bb * LC];
__device__ float g_sq[Bb * LQ];
__device__ float g_rowsum_part[Bb * 2 * LC];         // per q-tile partials
__device__ float g_rowsum[Bb * LC];
__device__ float g_colsum_part[Bb * 16 * LQ];        // per c-tile partials
__device__ float g_colsum[Bb * LQ];
__device__ float g_qmean[Bb * Dd];
__device__ float g_cmean_part[Bb * 8 * Dd];
__device__ float g_cmean[Bb * Dd];
__device__ float g_tmean[Bb * Dd];
__device__ unsigned char g_cm[Bb * LC];
__device__ unsigned char g_qm[Bb * LQ];
__device__ int g_is32;

// ---------------- mask dtype detection + canonicalization ----------------
// numpy bool -> 1 byte/elem (random 0/1 bytes). If harness widened to int32,
// every element is {v,0,0,0} little-endian -> bytes at (i%4!=0) are all zero.
__global__ void k_detect(const unsigned char* __restrict__ cm) {
    if (threadIdx.x == 0 && blockIdx.x == 0) {
        int is32 = 1;
        for (int i = 0; i < 4096; i++) {
            if ((i & 3) && cm[i]) { is32 = 0; break; }
        }
        g_is32 = is32;
    }
}

__global__ void k_cvt_mask(const void* __restrict__ cm, const void* __restrict__ qm) {
    int i = blockIdx.x * 256 + threadIdx.x;
    int is32 = g_is32;
    if (i < Bb * LC) {
        g_cm[i] = is32 ? (unsigned char)(((const int*)cm)[i] != 0)
                       : (unsigned char)(((const unsigned char*)cm)[i] != 0);
    }
    if (i < Bb * LQ) {
        g_qm[i] = is32 ? (unsigned char)(((const int*)qm)[i] != 0)
                       : (unsigned char)(((const unsigned char*)qm)[i] != 0);
    }
}

// ---------------- K0a: sc = context @ wc, sq = query @ wq ----------------
__global__ void k0_rowdots(const float* __restrict__ ctx, const float* __restrict__ qry,
                           const float* __restrict__ w0) {
    int warp = (blockIdx.x * blockDim.x + threadIdx.x) >> 5;
    int lane = threadIdx.x & 31;
    const int nC = Bb * LC;
    const float* src;
    const float* wgt;
    float* dst;
    if (warp < nC) {
        src = ctx + (size_t)warp * Dd; wgt = w0; dst = g_sc + warp;
    } else {
        int r = warp - nC;
        if (r >= Bb * LQ) return;
        src = qry + (size_t)r * Dd; wgt = w0 + Dd; dst = g_sq + r;
    }
    float s = 0.f;
#pragma unroll
    for (int i = 0; i < 2; i++) {
        int idx = (lane + 32 * i) * 4;
        float4 v = *(const float4*)(src + idx);
        float4 w = *(const float4*)(wgt + idx);
        s += v.x * w.x + v.y * w.y + v.z * w.z + v.w * w.w;
    }
#pragma unroll
    for (int o = 16; o; o >>= 1) s += __shfl_xor_sync(0xffffffffu, s, o);
    if (lane == 0) *dst = s;
}

// ---------------- K0b: qmean, cmean partials ----------------
__global__ void k0_means(const float* __restrict__ ctx, const float* __restrict__ qry) {
    int b = blockIdx.x, y = blockIdx.y, d = threadIdx.x;  // 256 threads = D
    if (y == 0) {
        const float* p = qry + (size_t)b * LQ * Dd + d;
        float s0 = 0, s1 = 0, s2 = 0, s3 = 0, s4 = 0, s5 = 0, s6 = 0, s7 = 0;
        for (int q = 0; q < LQ; q += 8) {
            s0 += p[(size_t)(q + 0) * Dd]; s1 += p[(size_t)(q + 1) * Dd];
            s2 += p[(size_t)(q + 2) * Dd]; s3 += p[(size_t)(q + 3) * Dd];
            s4 += p[(size_t)(q + 4) * Dd]; s5 += p[(size_t)(q + 5) * Dd];
            s6 += p[(size_t)(q + 6) * Dd]; s7 += p[(size_t)(q + 7) * Dd];
        }
        g_qmean[b * Dd + d] = (((s0 + s1) + (s2 + s3)) + ((s4 + s5) + (s6 + s7))) * (1.0f / LQ);
    } else {
        int chunk = y - 1;  // 8 chunks of 256 context rows
        const float* p = ctx + ((size_t)b * LC + chunk * 256) * Dd + d;
        float s0 = 0, s1 = 0, s2 = 0, s3 = 0, s4 = 0, s5 = 0, s6 = 0, s7 = 0;
        for (int c = 0; c < 256; c += 8) {
            s0 += p[(size_t)(c + 0) * Dd]; s1 += p[(size_t)(c + 1) * Dd];
            s2 += p[(size_t)(c + 2) * Dd]; s3 += p[(size_t)(c + 3) * Dd];
            s4 += p[(size_t)(c + 4) * Dd]; s5 += p[(size_t)(c + 5) * Dd];
            s6 += p[(size_t)(c + 6) * Dd]; s7 += p[(size_t)(c + 7) * Dd];
        }
        g_cmean_part[((size_t)b * 8 + chunk) * Dd + d] =
            ((s0 + s1) + (s2 + s3)) + ((s4 + s5) + (s6 + s7));
    }
}

// ---------------- K1: E = exp(sim) (masked -> 0) + row/col partial sums ----------------
__global__ __launch_bounds__(256)
void k1_exp(const float* __restrict__ ctx, const float* __restrict__ qry,
            const float* __restrict__ w0) {
    int b = blockIdx.z;
    int cblk = blockIdx.x * BM;   // 16 tiles
    int qblk = blockIdx.y * BN;   // 2 tiles
    __shared__ float As[KC][BM + PAD];
    __shared__ float Bs[KC][BN + PAD];
    __shared__ float colred[16][BN];
    int tid = threadIdx.x;
    int tx = tid & 15, ty = tid >> 4;
    float acc[8][8];
#pragma unroll
    for (int i = 0; i < 8; i++)
#pragma unroll
        for (int j = 0; j < 8; j++) acc[i][j] = 0.f;

    const float* wm = w0 + 2 * Dd;
    const float* Ap = ctx + ((size_t)b * LC + cblk) * Dd;
    const float* Bp = qry + ((size_t)b * LQ + qblk) * Dd;

    for (int k0 = 0; k0 < Dd; k0 += KC) {
#pragma unroll
        for (int r = 0; r < 4; r++) {
            int u = tid + 256 * r;          // 1024 float4 slots per matrix
            int row = u >> 3;
            int kq = (u & 7) * 4;
            float4 v = *(const float4*)(Ap + (size_t)row * Dd + k0 + kq);
            float4 w = *(const float4*)(wm + k0 + kq);
            As[kq + 0][row] = v.x * w.x; As[kq + 1][row] = v.y * w.y;
            As[kq + 2][row] = v.z * w.z; As[kq + 3][row] = v.w * w.w;
            float4 q4 = *(const float4*)(Bp + (size_t)row * Dd + k0 + kq);
            Bs[kq + 0][row] = q4.x; Bs[kq + 1][row] = q4.y;
            Bs[kq + 2][row] = q4.z; Bs[kq + 3][row] = q4.w;
        }
        __syncthreads();
#pragma unroll 4
        for (int kk = 0; kk < KC; kk++) {
            float a[8], bv[8];
            *(float4*)&a[0] = *(const float4*)&As[kk][ty * 8];
            *(float4*)&a[4] = *(const float4*)&As[kk][ty * 8 + 4];
            *(float4*)&bv[0] = *(const float4*)&Bs[kk][tx * 8];
            *(float4*)&bv[4] = *(const float4*)&Bs[kk][tx * 8 + 4];
#pragma unroll
            for (int i = 0; i < 8; i++)
#pragma unroll
                for (int j = 0; j < 8; j++) acc[i][j] += a[i] * bv[j];
        }
        __syncthreads();
    }

    // epilogue: sim = acc + sc + sq; mask; E = exp(sim)
    float sqv[8];
    int qmv[8];
#pragma unroll
    for (int j = 0; j < 8; j++) {
        int q = qblk + tx * 8 + j;
        sqv[j] = g_sq[b * LQ + q];
        qmv[j] = g_qm[b * LQ + q];
    }
    float colpart[8];
#pragma unroll
    for (int j = 0; j < 8; j++) colpart[j] = 0.f;

#pragma unroll
    for (int i = 0; i < 8; i++) {
        int c = cblk + ty * 8 + i;
        float scv = g_sc[b * LC + c];
        int cmv = g_cm[b * LC + c];
        float e[8];
        float rowp = 0.f;
#pragma unroll
        for (int j = 0; j < 8; j++) {
            float s = acc[i][j] + scv + sqv[j];
            float ev = (cmv | qmv[j]) ? 0.f : __expf(s);
            e[j] = ev;
            rowp += ev;
            colpart[j] += ev;
        }
        float* ep = g_E + ((size_t)(b * LC + c)) * LQ + qblk + tx * 8;
        *(float4*)ep       = make_float4(e[0], e[1], e[2], e[3]);
        *(float4*)(ep + 4) = make_float4(e[4], e[5], e[6], e[7]);
        // reduce over the 16 tx-lanes (same ty => same 16-lane segment)
#pragma unroll
        for (int o = 8; o; o >>= 1) rowp += __shfl_xor_sync(0xffffffffu, rowp, o, 16);
        if (tx == 0) g_rowsum_part[((size_t)b * 2 + blockIdx.y) * LC + c] = rowp;
    }
#pragma unroll
    for (int j = 0; j < 8; j++) colred[ty][tx * 8 + j] = colpart[j];
    __syncthreads();
    if (tid < BN) {
        float s = 0.f;
#pragma unroll
        for (int t = 0; t < 16; t++) s += colred[t][tid];
        g_colsum_part[((size_t)b * 16 + blockIdx.x) * LQ + qblk + tid] = s;
    }
}

// ---------------- K2: deterministic partial reductions ----------------
__global__ void k2_reduce() {
    int b = blockIdx.x, tid = threadIdx.x;  // 256 threads
    for (int c = tid; c < LC; c += 256) {
        g_rowsum[b * LC + c] = g_rowsum_part[((size_t)b * 2 + 0) * LC + c] +
                               g_rowsum_part[((size_t)b * 2 + 1) * LC + c];
    }
    {
        int q = tid;
        float s = 0.f;
#pragma unroll
        for (int t = 0; t < 16; t++) s += g_colsum_part[((size_t)b * 16 + t) * LQ + q];
        g_colsum[b * LQ + q] = s;
    }
    {
        int d = tid;
        float s = 0.f;
#pragma unroll
        for (int t = 0; t < 8; t++) s += g_cmean_part[((size_t)b * 8 + t) * Dd + d];
        g_cmean[b * Dd + d] = s * (1.0f / LC);
    }
}

// ---------------- K3: T[q][d] = (1/colsum) * sum_c E[c][q]*ctx[c][d] (fallback cmean) -----
__global__ __launch_bounds__(256)
void k3_T(const float* __restrict__ ctx) {
    int b = blockIdx.z;
    int qblk = blockIdx.x * BM;  // 2 tiles
    int dblk = blockIdx.y * BN;  // 2 tiles
    __shared__ float As[KC][BM + PAD];
    __shared__ float Bs[KC][BN + PAD];
    int tid = threadIdx.x, tx = tid & 15, ty = tid >> 4;
    float acc[8][8];
#pragma unroll
    for (int i = 0; i < 8; i++)
#pragma unroll
        for (int j = 0; j < 8; j++) acc[i][j] = 0.f;

    const float* Ep = g_E + (size_t)b * LC * LQ;
    const float* Cp = ctx + (size_t)b * LC * Dd;

    for (int k0 = 0; k0 < LC; k0 += KC) {
#pragma unroll
        for (int r = 0; r < 4; r++) {
            int u = tid + 256 * r;
            int kk = u >> 5;
            int m4 = (u & 31) * 4;
            *(float4*)&As[kk][m4] = *(const float4*)(Ep + (size_t)(k0 + kk) * LQ + qblk + m4);
            *(float4*)&Bs[kk][m4] = *(const float4*)(Cp + (size_t)(k0 + kk) * Dd + dblk + m4);
        }
        __syncthreads();
#pragma unroll 4
        for (int kk = 0; kk < KC; kk++) {
            float a[8], bv[8];
            *(float4*)&a[0] = *(const float4*)&As[kk][ty * 8];
            *(float4*)&a[4] = *(const float4*)&As[kk][ty * 8 + 4];
            *(float4*)&bv[0] = *(const float4*)&Bs[kk][tx * 8];
            *(float4*)&bv[4] = *(const float4*)&Bs[kk][tx * 8 + 4];
#pragma unroll
            for (int i = 0; i < 8; i++)
#pragma unroll
                for (int j = 0; j < 8; j++) acc[i][j] += a[i] * bv[j];
        }
        __syncthreads();
    }

#pragma unroll
    for (int i = 0; i < 8; i++) {
        int q = qblk + ty * 8 + i;
        float cs = g_colsum[b * LQ + q];
        float* Tp = g_T + ((size_t)b * LQ + q) * Dd + dblk + tx * 8;
        if (cs > 0.f) {
            float inv = 1.0f / cs;
            *(float4*)Tp = make_float4(acc[i][0] * inv, acc[i][1] * inv,
                                       acc[i][2] * inv, acc[i][3] * inv);
            *(float4*)(Tp + 4) = make_float4(acc[i][4] * inv, acc[i][5] * inv,
                                             acc[i][6] * inv, acc[i][7] * inv);
        } else {
            const float* fb = g_cmean + b * Dd + dblk + tx * 8;
            *(float4*)Tp = make_float4(fb[0], fb[1], fb[2], fb[3]);
            *(float4*)(Tp + 4) = make_float4(fb[4], fb[5], fb[6], fb[7]);
        }
    }
}

// ---------------- K3b: tmean = mean_q T ----------------
__global__ void k3b_tmean() {
    int b = blockIdx.x, d = threadIdx.x;  // 256 threads
    const float* p = g_T + (size_t)b * LQ * Dd + d;
    float s0 = 0, s1 = 0, s2 = 0, s3 = 0;
    for (int q = 0; q < LQ; q += 4) {
        s0 += p[(size_t)(q + 0) * Dd]; s1 += p[(size_t)(q + 1) * Dd];
        s2 += p[(size_t)(q + 2) * Dd]; s3 += p[(size_t)(q + 3) * Dd];
    }
    g_tmean[b * Dd + d] = ((s0 + s1) + (s2 + s3)) * (1.0f / LQ);
}

// ---------------- K4: A = E@query / rowsum ; Bmat = E@T / rowsum (uniform fallbacks) -----
__global__ __launch_bounds__(256)
void k4_out(const float* __restrict__ qry, float* __restrict__ out) {
    int b = blockIdx.z;
    int cblk = blockIdx.x * BM;              // 16 tiles
    int sel = blockIdx.y >> 1;               // 0 = A, 1 = Bmat
    int dblk = (blockIdx.y & 1) * BN;        // 2 tiles
    const float* Bsrc = sel ? (g_T + (size_t)b * LQ * Dd) : (qry + (size_t)b * LQ * Dd);
    const float* fb = (sel ? g_tmean : g_qmean) + b * Dd;
    float* op = out + (size_t)sel * Bb * LC * Dd + (size_t)b * LC * Dd;

    __shared__ float As[KC][BM + PAD];
    __shared__ float Bs[KC][BN + PAD];
    int tid = threadIdx.x, tx = tid & 15, ty = tid >> 4;
    float acc[8][8];
#pragma unroll
    for (int i = 0; i < 8; i++)
#pragma unroll
        for (int j = 0; j < 8; j++) acc[i][j] = 0.f;

    const float* Ep = g_E + ((size_t)b * LC + cblk) * LQ;

    for (int k0 = 0; k0 < LQ; k0 += KC) {
#pragma unroll
        for (int r = 0; r < 4; r++) {
            int u = tid + 256 * r;
            // A tile: E rows (k = q contiguous) -> transpose into As[k][m]
            int row = u >> 3;
            int kq = (u & 7) * 4;
            float4 v = *(const float4*)(Ep + (size_t)row * LQ + k0 + kq);
            As[kq + 0][row] = v.x; As[kq + 1][row] = v.y;
            As[kq + 2][row] = v.z; As[kq + 3][row] = v.w;
            // B tile: Bsrc[k=q][n=d] directly
            int kk = u >> 5;
            int m4 = (u & 31) * 4;
            *(float4*)&Bs[kk][m4] = *(const float4*)(Bsrc + (size_t)(k0 + kk) * Dd + dblk + m4);
        }
        __syncthreads();
#pragma unroll 4
        for (int kk = 0; kk < KC; kk++) {
            float a[8], bv[8];
            *(float4*)&a[0] = *(const float4*)&As[kk][ty * 8];
            *(float4*)&a[4] = *(const float4*)&As[kk][ty * 8 + 4];
            *(float4*)&bv[0] = *(const float4*)&Bs[kk][tx * 8];
            *(float4*)&bv[4] = *(const float4*)&Bs[kk][tx * 8 + 4];
#pragma unroll
            for (int i = 0; i < 8; i++)
#pragma unroll
                for (int j = 0; j < 8; j++) acc[i][j] += a[i] * bv[j];
        }
        __syncthreads();
    }

#pragma unroll
    for (int i = 0; i < 8; i++) {
        int c = cblk + ty * 8 + i;
        float rs = g_rowsum[b * LC + c];
        float* dst = op + (size_t)c * Dd + dblk + tx * 8;
        if (rs > 0.f) {
            float inv = 1.0f / rs;
            *(float4*)dst = make_float4(acc[i][0] * inv, acc[i][1] * inv,
                                        acc[i][2] * inv, acc[i][3] * inv);
            *(float4*)(dst + 4) = make_float4(acc[i][4] * inv, acc[i][5] * inv,
                                              acc[i][6] * inv, acc[i][7] * inv);
        } else {
            const float* f = fb + dblk + tx * 8;
            *(float4*)dst = make_float4(f[0], f[1], f[2], f[3]);
            *(float4*)(dst + 4) = make_float4(f[4], f[5], f[6], f[7]);
        }
    }
}

// ---------------- launcher ----------------
extern "C" void kernel_launch(void* const* d_in, const int* in_sizes, int n_in,
                              void* d_out, int out_size) {
    const float* ctx = (const float*)d_in[0];
    const float* qry = (const float*)d_in[1];
    const void* cmask = d_in[2];
    const void* qmask = d_in[3];
    const float* w0 = (const float*)d_in[4];
    float* out = (float*)d_out;

    k_detect<<<1, 32>>>((const unsigned char*)cmask);
    k_cvt_mask<<<(Bb * LC + 255) / 256, 256>>>(cmask, qmask);
    k0_rowdots<<<(Bb * (LC + LQ)) / 8, 256>>>(ctx, qry, w0);
    k0_means<<<dim3(Bb, 9), 256>>>(ctx, qry);
    k1_exp<<<dim3(LC / BM, LQ / BN, Bb), 256>>>(ctx, qry, w0);
    k2_reduce<<<Bb, 256>>>();
    k3_T<<<dim3(LQ / BM, Dd / BN, Bb), 256>>>(ctx);
    k3b_tmean<<<Bb, 256>>>();
    k4_out<<<dim3(LC / BM, 4, Bb), 256>>>(qry, out);
}